// round 13
// baseline (speedup 1.0000x reference)
#include <cuda_runtime.h>
#include <cstdint>

// ---------------- problem dims ----------------
static constexpr int BATCH = 16;
static constexpr int HWD   = 64;
static constexpr int CH    = 256;           // Cin = Cout
static constexpr int KTOT  = 9 * CH;        // 2304
static constexpr int KCH   = 32;            // K per chunk
static constexpr int NCHUNK = KTOT / KCH;   // 72
static constexpr int AS    = 36;            // smem row stride (floats) -> conflict-free

static constexpr int NTILES = BATCH * 32;       // 512 (M128 x N256 tiles)
static constexpr int GRID_PERSIST = 304;        // 2 CTAs x 152 SMs (GB300)

// ---------------- device scratch ----------------
__device__ float g_K2[CH * CH];
__device__ float g_d[BATCH * CH];
__device__ float g_B[NCHUNK * CH * KCH];    // [chunk][co][kperm] tf32-rounded
__device__ unsigned int g_tile_ctr;

// smem layout (floats): s[256] | d[256] | A 2x(128*36) | B 2x(256*36)
static constexpr int SM_S = 0;
static constexpr int SM_D = 256;
static constexpr int SM_A = 512;
static constexpr int A_BUF = 128 * AS;      // 4608 floats
static constexpr int SM_B = SM_A + 2 * A_BUF;
static constexpr int B_BUF = 256 * AS;      // 9216 floats
static constexpr int SMEM_FLOATS = SM_B + 2 * B_BUF;   // 28160
static constexpr int SMEM_BYTES  = SMEM_FLOATS * 4;    // 112640 -> 2 CTAs = 225.3KB

// ---------------- helpers ----------------
__device__ __forceinline__ float to_tf32(float v) {
    uint32_t u;
    asm("cvt.rna.tf32.f32 %0, %1;" : "=r"(u) : "f"(v));
    return __uint_as_float(u);
}
__device__ __forceinline__ uint32_t smem_u32(const void* p) {
    uint32_t a;
    asm("{ .reg .u64 t; cvta.to.shared.u64 t, %1; cvt.u32.u64 %0, t; }" : "=r"(a) : "l"(p));
    return a;
}
__device__ __forceinline__ void cp16(uint32_t dst_smem, const void* src) {
    asm volatile("cp.async.cg.shared.global [%0], [%1], 16;" :: "r"(dst_smem), "l"(src));
}
__device__ __forceinline__ void cp_commit() {
    asm volatile("cp.async.commit_group;" ::: "memory");
}
__device__ __forceinline__ void cp_wait0() {
    asm volatile("cp.async.wait_group 0;" ::: "memory");
}
__device__ __forceinline__ void mma_tf32(float* c, const uint32_t* a, const uint32_t* b) {
    asm volatile(
        "mma.sync.aligned.m16n8k8.row.col.f32.tf32.tf32.f32 "
        "{%0,%1,%2,%3}, {%4,%5,%6,%7}, {%8,%9}, {%0,%1,%2,%3};"
        : "+f"(c[0]), "+f"(c[1]), "+f"(c[2]), "+f"(c[3])
        : "r"(a[0]), "r"(a[1]), "r"(a[2]), "r"(a[3]), "r"(b[0]), "r"(b[1]));
}

// ---------------- prep kernels ----------------
__global__ void k2_kernel(const float* __restrict__ kern) {
    int co = threadIdx.x, ci = blockIdx.x;
    float acc = 0.f;
#pragma unroll
    for (int tap = 0; tap < 9; tap++) {
        float v = kern[(tap * CH + ci) * CH + co];
        acc += v * v;
    }
    g_K2[ci * CH + co] = acc;
}

__global__ void d_kernel(const float* __restrict__ style) {
    __shared__ float s2[CH];
    int b = blockIdx.x, t = threadIdx.x;
    float s = style[b * CH + t] + 1.0f;
    s2[t] = s * s;
    __syncthreads();
    float acc = 0.f;
#pragma unroll 8
    for (int ci = 0; ci < CH; ci++) acc += s2[ci] * g_K2[ci * CH + t];
    g_d[b * CH + t] = rsqrtf(acc + 1e-8f);
}

// pack kernel -> [chunk][co][kperm] tf32; also reset the persistent tile counter.
__global__ void bprep_kernel(const float* __restrict__ kern) {
    if (blockIdx.x == 0 && threadIdx.x == 0) g_tile_ctr = 0u;
    int e = blockIdx.x * 256 + threadIdx.x;   // 589824
    int co = e & 255;
    int k  = e >> 8;                          // tap*256 + ci
    int chunk = k >> 5, kk = k & 31;
    int p = 8 * (kk & 3) + (kk >> 2);
    g_B[(size_t)chunk * (CH * KCH) + co * KCH + p] = to_tf32(kern[k * CH + co]);
}

// ---------------- main kernel ----------------
// Persistent: 304 CTAs pop 512 tiles (M=128 x N=256, K=2304).
// 256 threads = 8 warps (2 M x 4 N), warp tile 64 x 64. 2 CTAs/SM -> 16 warps/SM.
__global__ void __launch_bounds__(256, 2) conv_kernel(
    const float* __restrict__ x, const float* __restrict__ style, float* __restrict__ y) {
    extern __shared__ float sm[];
    __shared__ int s_tile;
    float* s_s = sm + SM_S;
    float* s_d = sm + SM_D;
    float* sA  = sm + SM_A;
    float* sB  = sm + SM_B;
    const uint32_t sB_u32 = smem_u32(sB);

    const int tid  = threadIdx.x;
    const int lane = tid & 31;
    const int wid  = tid >> 5;
    const int wm = wid & 1, wn = wid >> 1;     // 2 x 4 warp grid
    const int m0 = wm * 64, n0 = wn * 64;
    const int gi = lane >> 2, ti = lane & 3;
    const int r_base = tid >> 3;               // A staging row: r_base + j*32
    const int v_     = tid & 7;

    float4 ar[4];
    int a_ci0 = 0;

#define LOAD_A(chunk)                                                              \
    {                                                                              \
        int tap = (chunk) >> 3, sub = (chunk) & 7;                                 \
        int kh = tap / 3 - 1, kw = tap % 3 - 1;                                    \
        a_ci0 = sub * KCH;                                                         \
        _Pragma("unroll")                                                          \
        for (int j = 0; j < 4; j++) {                                              \
            int r = r_base + j * 32;                                               \
            int hi = h0 + (r >> 6) + kh, wi = (r & 63) + kw;                       \
            ar[j] = make_float4(0.f, 0.f, 0.f, 0.f);                               \
            if ((unsigned)hi < (unsigned)HWD && (unsigned)wi < (unsigned)HWD)      \
                ar[j] = *(const float4*)(xb + ((size_t)(hi * HWD + wi)) * CH + a_ci0 + v_ * 4); \
        }                                                                          \
    }

#define STORE_A(sbuf)                                                              \
    {                                                                              \
        float* abuf = sA + (sbuf) * A_BUF;                                         \
        float4 sv = *(const float4*)(s_s + a_ci0 + v_ * 4);                        \
        _Pragma("unroll")                                                          \
        for (int j = 0; j < 4; j++) {                                              \
            float4 o;                                                              \
            o.x = to_tf32(ar[j].x * sv.x); o.y = to_tf32(ar[j].y * sv.y);          \
            o.z = to_tf32(ar[j].z * sv.z); o.w = to_tf32(ar[j].w * sv.w);          \
            *(float4*)(abuf + (r_base + j * 32) * AS + v_ * 4) = o;                \
        }                                                                          \
    }

#define LOAD_B(chunk, sbuf)                                                        \
    {                                                                              \
        const float* gb = g_B + (size_t)(chunk) * (CH * KCH);                      \
        uint32_t base = sB_u32 + (uint32_t)(sbuf) * (B_BUF * 4);                   \
        _Pragma("unroll")                                                          \
        for (int j = 0; j < 8; j++) {                                              \
            int u = j * 256 + tid;                                                 \
            int row = u >> 3, seg = u & 7;                                         \
            cp16(base + (uint32_t)(row * (AS * 4) + seg * 16), gb + u * 4);        \
        }                                                                          \
        cp_commit();                                                               \
    }

// one half = 8 B LDS.128 + 2 kf x 4 mi x (4 A LDS.32 + 8 HMMA)
#define MMA_HALF(half)                                                             \
    {                                                                              \
        float4 bq[8];                                                              \
        _Pragma("unroll")                                                          \
        for (int ni = 0; ni < 8; ni++)                                             \
            bq[ni] = *(const float4*)(Bw + ni * 8 * AS + (half) * 4);              \
        _Pragma("unroll")                                                          \
        for (int kf2 = 0; kf2 < 2; kf2++) {                                        \
            const int k0 = ((half) * 2 + kf2) * 8;                                 \
            _Pragma("unroll")                                                      \
            for (int mi = 0; mi < 4; mi++) {                                       \
                const float* ap = Aw + mi * (16 * AS) + k0;                        \
                uint32_t af[4];                                                    \
                af[0] = __float_as_uint(ap[0]);                                    \
                af[1] = __float_as_uint(ap[8 * AS]);                               \
                af[2] = __float_as_uint(ap[4]);                                    \
                af[3] = __float_as_uint(ap[8 * AS + 4]);                           \
                _Pragma("unroll")                                                  \
                for (int ni = 0; ni < 8; ni++) {                                   \
                    uint32_t bf[2];                                                \
                    bf[0] = __float_as_uint(kf2 ? bq[ni].z : bq[ni].x);            \
                    bf[1] = __float_as_uint(kf2 ? bq[ni].w : bq[ni].y);            \
                    mma_tf32(acc[mi][ni], af, bf);                                 \
                }                                                                  \
            }                                                                      \
        }                                                                          \
    }

    for (;;) {
        __syncthreads();                      // previous tile fully done
        if (tid == 0) s_tile = (int)atomicAdd(&g_tile_ctr, 1u);
        __syncthreads();
        const int t = s_tile;
        if (t >= NTILES) break;

        const int b  = t >> 5;
        const int mt = t & 31;
        const int h0 = mt * 2;
        const float* xb = x + (size_t)b * HWD * HWD * CH;

        if (tid < CH) {
            s_s[tid] = style[b * CH + tid] + 1.0f;
            s_d[tid] = g_d[b * CH + tid];
        }

        LOAD_A(0);
        LOAD_B(0, 0);
        __syncthreads();                      // s_s visible before STORE_A
        STORE_A(0);
        LOAD_A(1);

        float acc[4][8][4];
#pragma unroll
        for (int mi = 0; mi < 4; mi++)
#pragma unroll
            for (int ni = 0; ni < 8; ni++)
#pragma unroll
                for (int c = 0; c < 4; c++) acc[mi][ni][c] = 0.f;

        for (int i = 0; i < NCHUNK; i++) {
            const int s = i & 1;
            cp_wait0();
            __syncthreads();                 // buf s: A(i) (stored a chunk ago), B(i)
            if (i + 1 < NCHUNK) LOAD_B(i + 1, s ^ 1);

            const float* Aw = sA + s * A_BUF + (m0 + gi) * AS + ti;
            const float* Bw = sB + s * B_BUF + (n0 + gi) * AS + 8 * ti;

            MMA_HALF(0)
            if (i + 1 < NCHUNK) STORE_A(s ^ 1);   // WAR-safe via this iter's barrier
            if (i + 2 < NCHUNK) LOAD_A(i + 2);
            MMA_HALF(1)
        }

        // ---- epilogue: demodulate + store NHWC ----
#pragma unroll
        for (int mi = 0; mi < 4; mi++) {
            const int ma = m0 + mi * 16 + gi;
            const int mb = ma + 8;
            float* ya  = y + (((size_t)b * HWD + (h0 + (ma >> 6))) * HWD + (ma & 63)) * CH;
            float* yb2 = y + (((size_t)b * HWD + (h0 + (mb >> 6))) * HWD + (mb & 63)) * CH;
#pragma unroll
            for (int ni = 0; ni < 8; ni++) {
                const int col = n0 + ni * 8 + 2 * ti;   // global co (0..255)
                const float d0 = s_d[col], d1 = s_d[col + 1];
                float2 oa, ob;
                oa.x = acc[mi][ni][0] * d0; oa.y = acc[mi][ni][1] * d1;
                ob.x = acc[mi][ni][2] * d0; ob.y = acc[mi][ni][3] * d1;
                *(float2*)(ya + col)  = oa;
                *(float2*)(yb2 + col) = ob;
            }
        }
    }
#undef LOAD_A
#undef STORE_A
#undef LOAD_B
#undef MMA_HALF
}

// ---------------- launch ----------------
extern "C" void kernel_launch(void* const* d_in, const int* in_sizes, int n_in,
                              void* d_out, int out_size) {
    const float* x     = (const float*)d_in[0];   // [16,64,64,256]
    const float* style = (const float*)d_in[1];   // [16,256]
    const float* kern  = (const float*)d_in[2];   // [3,3,256,256]
    float* y = (float*)d_out;                     // [16,64,64,256]

    static bool attr_set = false;
    if (!attr_set) {
        cudaFuncSetAttribute(conv_kernel, cudaFuncAttributeMaxDynamicSharedMemorySize, SMEM_BYTES);
        attr_set = true;
    }

    k2_kernel<<<CH, CH>>>(kern);
    d_kernel<<<BATCH, CH>>>(style);
    bprep_kernel<<<KTOT, 256>>>(kern);   // also resets g_tile_ctr
    conv_kernel<<<GRID_PERSIST, 256, SMEM_BYTES>>>(x, style, y);
}

// round 15
// speedup vs baseline: 3.3984x; 3.3984x over previous
#include <cuda_runtime.h>
#include <cstdint>

// ---------------- problem dims ----------------
static constexpr int BATCH = 16;
static constexpr int HWD   = 64;
static constexpr int CH    = 256;           // Cin = Cout
static constexpr int KTOT  = 9 * CH;        // 2304
static constexpr int KCH   = 32;            // K per chunk
static constexpr int NCHUNK = KTOT / KCH;   // 72
static constexpr int AS    = 36;            // smem row stride (floats) -> conflict-free

static constexpr int CTA_N = 128;
static constexpr int NTILES = BATCH * 64 * 2;   // 2048 (M64 x N128 tiles)

// ---------------- device scratch ----------------
__device__ float g_K2[CH * CH];
__device__ float g_d[BATCH * CH];
__device__ float g_B[NCHUNK * CH * KCH];    // [chunk][co][kperm] tf32-rounded

// smem layout (floats): s[256] | d[128] | A 2x(64*36) | B 2x(128*36)
static constexpr int SM_S = 0;
static constexpr int SM_D = 256;
static constexpr int SM_A = 384;
static constexpr int A_BUF = 64 * AS;       // 2304 floats
static constexpr int SM_B = SM_A + 2 * A_BUF;
static constexpr int B_BUF = 128 * AS;      // 4608 floats
static constexpr int SMEM_FLOATS = SM_B + 2 * B_BUF;   // 14208
static constexpr int SMEM_BYTES  = SMEM_FLOATS * 4;    // 56832 -> 3 CTAs/SM

// ---------------- helpers ----------------
__device__ __forceinline__ float to_tf32(float v) {
    uint32_t u;
    asm("cvt.rna.tf32.f32 %0, %1;" : "=r"(u) : "f"(v));
    return __uint_as_float(u);
}
__device__ __forceinline__ uint32_t smem_u32(const void* p) {
    uint32_t a;
    asm("{ .reg .u64 t; cvta.to.shared.u64 t, %1; cvt.u32.u64 %0, t; }" : "=r"(a) : "l"(p));
    return a;
}
__device__ __forceinline__ void cp16(uint32_t dst_smem, const void* src) {
    asm volatile("cp.async.cg.shared.global [%0], [%1], 16;" :: "r"(dst_smem), "l"(src));
}
__device__ __forceinline__ void cp_commit() {
    asm volatile("cp.async.commit_group;" ::: "memory");
}
__device__ __forceinline__ void cp_wait0() {
    asm volatile("cp.async.wait_group 0;" ::: "memory");
}
__device__ __forceinline__ void mma_tf32(float* c, const uint32_t* a, const uint32_t* b) {
    asm volatile(
        "mma.sync.aligned.m16n8k8.row.col.f32.tf32.tf32.f32 "
        "{%0,%1,%2,%3}, {%4,%5,%6,%7}, {%8,%9}, {%0,%1,%2,%3};"
        : "+f"(c[0]), "+f"(c[1]), "+f"(c[2]), "+f"(c[3])
        : "r"(a[0]), "r"(a[1]), "r"(a[2]), "r"(a[3]), "r"(b[0]), "r"(b[1]));
}

// ---------------- prep kernels ----------------
__global__ void k2_kernel(const float* __restrict__ kern) {
    int co = threadIdx.x, ci = blockIdx.x;
    float acc = 0.f;
#pragma unroll
    for (int tap = 0; tap < 9; tap++) {
        float v = kern[(tap * CH + ci) * CH + co];
        acc += v * v;
    }
    g_K2[ci * CH + co] = acc;
}

__global__ void d_kernel(const float* __restrict__ style) {
    __shared__ float s2[CH];
    int b = blockIdx.x, t = threadIdx.x;
    float s = style[b * CH + t] + 1.0f;
    s2[t] = s * s;
    __syncthreads();
    float acc = 0.f;
#pragma unroll 8
    for (int ci = 0; ci < CH; ci++) acc += s2[ci] * g_K2[ci * CH + t];
    g_d[b * CH + t] = rsqrtf(acc + 1e-8f);
}

// pack kernel -> [chunk][co][kperm] tf32. perm p = 8*(k&3)+(k>>2) within 32.
__global__ void bprep_kernel(const float* __restrict__ kern) {
    int e = blockIdx.x * 256 + threadIdx.x;   // 589824
    int co = e & 255;
    int k  = e >> 8;                          // tap*256 + ci
    int chunk = k >> 5, kk = k & 31;
    int p = 8 * (kk & 3) + (kk >> 2);
    g_B[(size_t)chunk * (CH * KCH) + co * KCH + p] = to_tf32(kern[k * CH + co]);
}

// ---------------- main kernel ----------------
// Grid: 2048 CTAs = 16 b x 64 mtiles x 2 ntiles. CTA: M=64 (1 row) x N=128, K=2304.
// 128 threads = 4 warps (2 M x 2 N), warp tile 32 x 64. 3 CTAs/SM -> 12 warps/SM.
__global__ void __launch_bounds__(128, 3) conv_kernel(
    const float* __restrict__ x, const float* __restrict__ style, float* __restrict__ y) {
    extern __shared__ float sm[];
    float* s_s = sm + SM_S;
    float* s_d = sm + SM_D;
    float* sA  = sm + SM_A;
    float* sB  = sm + SM_B;
    const uint32_t sB_u32 = smem_u32(sB);

    const int tid  = threadIdx.x;
    const int lane = tid & 31;
    const int wid  = tid >> 5;
    const int b    = blockIdx.x >> 7;
    const int mt   = (blockIdx.x >> 1) & 63;    // output row h0
    const int nt   = blockIdx.x & 1;
    const int h0   = mt;
    const int co0  = nt * CTA_N;

    for (int i = tid; i < CH; i += 128) s_s[i] = style[b * CH + i] + 1.0f;
    if (tid < CTA_N) s_d[tid] = g_d[b * CH + co0 + tid];
    __syncthreads();

    const float* xb = x + (size_t)b * HWD * HWD * CH;

    // A staging regs: 64 pixels x 32 floats = 512 float4, 4 per thread
    float4 ar[4];
    int a_ci0 = 0;
    const int p_base = tid >> 3;          // pixel for j: p_base + j*16
    const int v_     = tid & 7;

#define LOAD_A(chunk)                                                              \
    {                                                                              \
        int tap = (chunk) >> 3, sub = (chunk) & 7;                                 \
        int kh = tap / 3 - 1, kw = tap % 3 - 1;                                    \
        a_ci0 = sub * KCH;                                                         \
        int hi = h0 + kh;                                                          \
        _Pragma("unroll")                                                          \
        for (int j = 0; j < 4; j++) {                                              \
            int wi = p_base + j * 16 + kw;                                         \
            ar[j] = make_float4(0.f, 0.f, 0.f, 0.f);                               \
            if ((unsigned)hi < (unsigned)HWD && (unsigned)wi < (unsigned)HWD)      \
                ar[j] = *(const float4*)(xb + ((size_t)(hi * HWD + wi)) * CH + a_ci0 + v_ * 4); \
        }                                                                          \
    }

#define STORE_A(sbuf)                                                              \
    {                                                                              \
        float* abuf = sA + (sbuf) * A_BUF;                                         \
        float4 sv = *(const float4*)(s_s + a_ci0 + v_ * 4);                        \
        _Pragma("unroll")                                                          \
        for (int j = 0; j < 4; j++) {                                              \
            float4 o;                                                              \
            o.x = to_tf32(ar[j].x * sv.x); o.y = to_tf32(ar[j].y * sv.y);          \
            o.z = to_tf32(ar[j].z * sv.z); o.w = to_tf32(ar[j].w * sv.w);          \
            *(float4*)(abuf + (p_base + j * 16) * AS + v_ * 4) = o;                \
        }                                                                          \
    }

#define LOAD_B(chunk, sbuf)                                                        \
    {                                                                              \
        const float* gb = g_B + (size_t)(chunk) * (CH * KCH) + (size_t)co0 * KCH;  \
        uint32_t base = sB_u32 + (uint32_t)(sbuf) * (B_BUF * 4);                   \
        _Pragma("unroll")                                                          \
        for (int j = 0; j < 8; j++) {                                              \
            int u = j * 128 + tid;                                                 \
            int row = u >> 3, seg = u & 7;                                         \
            cp16(base + (uint32_t)(row * (AS * 4) + seg * 16), gb + u * 4);        \
        }                                                                          \
        cp_commit();                                                               \
    }

    // warp tiling: 2 wm x 2 wn, warp tile 32 x 64
    const int wm = wid & 1, wn = wid >> 1;
    const int m0 = wm * 32, n0 = wn * 64;
    const int gi = lane >> 2, ti = lane & 3;

    float acc[2][8][4];
#pragma unroll
    for (int mi = 0; mi < 2; mi++)
#pragma unroll
        for (int ni = 0; ni < 8; ni++)
#pragma unroll
            for (int c = 0; c < 4; c++) acc[mi][ni][c] = 0.f;

// one half = 8 B LDS.128 + 2 kf x 2 mi x (4 A LDS.32 + 8 HMMA)
#define MMA_HALF(half)                                                             \
    {                                                                              \
        float4 bq[8];                                                              \
        _Pragma("unroll")                                                          \
        for (int ni = 0; ni < 8; ni++)                                             \
            bq[ni] = *(const float4*)(Bw + ni * 8 * AS + (half) * 4);              \
        _Pragma("unroll")                                                          \
        for (int kf2 = 0; kf2 < 2; kf2++) {                                        \
            const int k0 = ((half) * 2 + kf2) * 8;                                 \
            _Pragma("unroll")                                                      \
            for (int mi = 0; mi < 2; mi++) {                                       \
                const float* ap = Aw + mi * (16 * AS) + k0;                        \
                uint32_t af[4];                                                    \
                af[0] = __float_as_uint(ap[0]);                                    \
                af[1] = __float_as_uint(ap[8 * AS]);                               \
                af[2] = __float_as_uint(ap[4]);                                    \
                af[3] = __float_as_uint(ap[8 * AS + 4]);                           \
                _Pragma("unroll")                                                  \
                for (int ni = 0; ni < 8; ni++) {                                   \
                    uint32_t bf[2];                                                \
                    bf[0] = __float_as_uint(kf2 ? bq[ni].z : bq[ni].x);            \
                    bf[1] = __float_as_uint(kf2 ? bq[ni].w : bq[ni].y);            \
                    mma_tf32(acc[mi][ni], af, bf);                                 \
                }                                                                  \
            }                                                                      \
        }                                                                          \
    }

    // prologue: A(0) staged into buf0; A(1) in regs; B(0) in flight
    LOAD_A(0);
    STORE_A(0);
    LOAD_A(1);
    LOAD_B(0, 0);

    for (int i = 0; i < NCHUNK; i++) {
        const int s = i & 1;
        cp_wait0();
        __syncthreads();                 // buf s: A(i) (stored a chunk ago), B(i)
        if (i + 1 < NCHUNK) LOAD_B(i + 1, s ^ 1);

        const float* Aw = sA + s * A_BUF + (m0 + gi) * AS + ti;
        const float* Bw = sB + s * B_BUF + (n0 + gi) * AS + 8 * ti;

        MMA_HALF(0)
        if (i + 1 < NCHUNK) STORE_A(s ^ 1);   // WAR-safe via this iter's barrier
        if (i + 2 < NCHUNK) LOAD_A(i + 2);
        MMA_HALF(1)
    }

    // ---- epilogue: demodulate + store NHWC ----
#pragma unroll
    for (int mi = 0; mi < 2; mi++) {
        const int wa = m0 + mi * 16 + gi;       // w coords wa and wa+8, row h0
        float* ya  = y + (((size_t)b * HWD + h0) * HWD + wa) * CH + co0;
        float* yb2 = ya + 8 * CH;
#pragma unroll
        for (int ni = 0; ni < 8; ni++) {
            const int col = n0 + ni * 8 + 2 * ti;   // local co
            const float d0 = s_d[col], d1 = s_d[col + 1];
            float2 oa, ob;
            oa.x = acc[mi][ni][0] * d0; oa.y = acc[mi][ni][1] * d1;
            ob.x = acc[mi][ni][2] * d0; ob.y = acc[mi][ni][3] * d1;
            *(float2*)(ya + col)  = oa;
            *(float2*)(yb2 + col) = ob;
        }
    }
#undef LOAD_A
#undef STORE_A
#undef LOAD_B
#undef MMA_HALF
}

// ---------------- launch ----------------
extern "C" void kernel_launch(void* const* d_in, const int* in_sizes, int n_in,
                              void* d_out, int out_size) {
    const float* x     = (const float*)d_in[0];   // [16,64,64,256]
    const float* style = (const float*)d_in[1];   // [16,256]
    const float* kern  = (const float*)d_in[2];   // [3,3,256,256]
    float* y = (float*)d_out;                     // [16,64,64,256]

    static bool attr_set = false;
    if (!attr_set) {
        cudaFuncSetAttribute(conv_kernel, cudaFuncAttributeMaxDynamicSharedMemorySize, SMEM_BYTES);
        attr_set = true;
    }

    k2_kernel<<<CH, CH>>>(kern);
    d_kernel<<<BATCH, CH>>>(style);
    bprep_kernel<<<KTOT, 256>>>(kern);
    conv_kernel<<<NTILES, 128, SMEM_BYTES>>>(x, style, y);
}

// round 16
// speedup vs baseline: 3.8026x; 1.1189x over previous
#include <cuda_runtime.h>
#include <cstdint>

// ---------------- problem dims ----------------
static constexpr int BATCH = 16;
static constexpr int HWD   = 64;
static constexpr int CH    = 256;           // Cin = Cout
static constexpr int KTOT  = 9 * CH;        // 2304
static constexpr int KCH   = 32;            // K per chunk
static constexpr int NCHUNK = KTOT / KCH;   // 72
static constexpr int AS    = 36;            // smem row stride (floats) -> conflict-free

static constexpr int CTA_N = 128;

// ---------------- device scratch ----------------
__device__ float g_K2[CH * CH];
__device__ float g_d[BATCH * CH];
// per-batch modulated B: [b][chunk][co][kperm], tf32-rounded (37.7 MB)
__device__ float g_Bs[(size_t)BATCH * NCHUNK * CH * KCH];

// smem layout (floats): d[128] | A 2x(128*36) | B 2x(128*36)
static constexpr int SM_D = 0;
static constexpr int SM_A = 128;
static constexpr int A_BUF = 128 * AS;      // 4608 floats
static constexpr int SM_B = SM_A + 2 * A_BUF;
static constexpr int B_BUF = 128 * AS;      // 4608 floats
static constexpr int SMEM_FLOATS = SM_B + 2 * B_BUF;   // 18560
static constexpr int SMEM_BYTES  = SMEM_FLOATS * 4;    // 74240 -> 2 CTAs/SM

// ---------------- helpers ----------------
__device__ __forceinline__ float to_tf32(float v) {
    uint32_t u;
    asm("cvt.rna.tf32.f32 %0, %1;" : "=r"(u) : "f"(v));
    return __uint_as_float(u);
}
__device__ __forceinline__ uint32_t smem_u32(const void* p) {
    uint32_t a;
    asm("{ .reg .u64 t; cvta.to.shared.u64 t, %1; cvt.u32.u64 %0, t; }" : "=r"(a) : "l"(p));
    return a;
}
__device__ __forceinline__ void cp16(uint32_t dst_smem, const void* src) {
    asm volatile("cp.async.cg.shared.global [%0], [%1], 16;" :: "r"(dst_smem), "l"(src));
}
// zero-fill variant: copies sz bytes from src, zero-fills the rest of 16
__device__ __forceinline__ void cp16z(uint32_t dst_smem, const void* src, int sz) {
    asm volatile("cp.async.cg.shared.global [%0], [%1], 16, %2;"
                 :: "r"(dst_smem), "l"(src), "r"(sz));
}
__device__ __forceinline__ void cp_commit() {
    asm volatile("cp.async.commit_group;" ::: "memory");
}
__device__ __forceinline__ void cp_wait0() {
    asm volatile("cp.async.wait_group 0;" ::: "memory");
}
__device__ __forceinline__ void mma_tf32(float* c, const uint32_t* a, const uint32_t* b) {
    asm volatile(
        "mma.sync.aligned.m16n8k8.row.col.f32.tf32.tf32.f32 "
        "{%0,%1,%2,%3}, {%4,%5,%6,%7}, {%8,%9}, {%0,%1,%2,%3};"
        : "+f"(c[0]), "+f"(c[1]), "+f"(c[2]), "+f"(c[3])
        : "r"(a[0]), "r"(a[1]), "r"(a[2]), "r"(a[3]), "r"(b[0]), "r"(b[1]));
}

// ---------------- prep kernels ----------------
__global__ void k2_kernel(const float* __restrict__ kern) {
    int co = threadIdx.x, ci = blockIdx.x;
    float acc = 0.f;
#pragma unroll
    for (int tap = 0; tap < 9; tap++) {
        float v = kern[(tap * CH + ci) * CH + co];
        acc += v * v;
    }
    g_K2[ci * CH + co] = acc;
}

__global__ void d_kernel(const float* __restrict__ style) {
    __shared__ float s2[CH];
    int b = blockIdx.x, t = threadIdx.x;
    float s = style[b * CH + t] + 1.0f;
    s2[t] = s * s;
    __syncthreads();
    float acc = 0.f;
#pragma unroll 8
    for (int ci = 0; ci < CH; ci++) acc += s2[ci] * g_K2[ci * CH + t];
    g_d[b * CH + t] = rsqrtf(acc + 1e-8f);
}

// per-batch modulated B pack: g_Bs[b][chunk][co][kperm] = tf32(kern * (style+1))
// perm p = 8*(k&3)+(k>>2) within the 32-wide chunk.
__global__ void bsprep_kernel(const float* __restrict__ kern, const float* __restrict__ style) {
    int e = blockIdx.x * 256 + threadIdx.x;   // 9,437,184
    int co   = e & 255;
    int rest = e >> 8;                        // b*KTOT + k
    int k = rest % KTOT;
    int b = rest / KTOT;
    int ci = k & 255;                         // k = tap*256 + ci
    int chunk = k >> 5, kk = k & 31;
    int p = 8 * (kk & 3) + (kk >> 2);
    float v = kern[(size_t)k * CH + co] * (style[b * CH + ci] + 1.0f);
    g_Bs[((size_t)b * NCHUNK + chunk) * (CH * KCH) + co * KCH + p] = to_tf32(v);
}

// ---------------- main kernel ----------------
// Grid: 1024 CTAs = 16 b x 32 mtiles x 2 ntiles. CTA: M=128 x N=128, K=2304.
// 128 threads = 4 warps (2 M x 2 N), warp tile 64 x 64. 2 CTAs/SM.
// A raw x via zero-fill cp.async (modulation folded into B). Low reg pressure.
__global__ void __launch_bounds__(128, 2) conv_kernel(
    const float* __restrict__ x, float* __restrict__ y) {
    extern __shared__ float sm[];
    float* s_d = sm + SM_D;
    float* sA  = sm + SM_A;
    float* sB  = sm + SM_B;
    const uint32_t sA_u32 = smem_u32(sA);
    const uint32_t sB_u32 = smem_u32(sB);

    const int tid  = threadIdx.x;
    const int lane = tid & 31;
    const int wid  = tid >> 5;
    const int b    = blockIdx.x >> 6;
    const int mt   = (blockIdx.x >> 1) & 31;
    const int nt   = blockIdx.x & 1;
    const int h0   = mt * 2;
    const int co0  = nt * CTA_N;

    if (tid < CTA_N) s_d[tid] = g_d[b * CH + co0 + tid];

    const float* xb  = x + (size_t)b * HWD * HWD * CH;
    const float* gbs = g_Bs + ((size_t)b * NCHUNK) * (CH * KCH) + (size_t)co0 * KCH;

    const int r_base = tid >> 3;          // A row for j: r_base + j*16
    const int v_     = tid & 7;           // 16B segment

// stage A (zero-fill cp.async from raw x) + B (from g_Bs); one commit
#define LOAD_AB(chunk, sbuf)                                                       \
    {                                                                              \
        int tap = (chunk) >> 3, sub = (chunk) & 7;                                 \
        int kh = tap / 3 - 1, kw = tap % 3 - 1;                                    \
        int ci0 = sub * KCH;                                                       \
        uint32_t abase = sA_u32 + (uint32_t)(sbuf) * (A_BUF * 4);                  \
        _Pragma("unroll")                                                          \
        for (int j = 0; j < 8; j++) {                                              \
            int r = r_base + j * 16;                                               \
            int hi = h0 + (r >> 6) + kh, wi = (r & 63) + kw;                       \
            int ok = ((unsigned)hi < (unsigned)HWD) & ((unsigned)wi < (unsigned)HWD); \
            int hc = ok ? hi : 0, wc = ok ? wi : 0;                                \
            cp16z(abase + (uint32_t)((r * AS + v_ * 4) * 4),                       \
                  xb + ((size_t)(hc * HWD + wc)) * CH + ci0 + v_ * 4, ok ? 16 : 0);\
        }                                                                          \
        const float* gb = gbs + (size_t)(chunk) * (CH * KCH);                      \
        uint32_t bbase = sB_u32 + (uint32_t)(sbuf) * (B_BUF * 4);                  \
        _Pragma("unroll")                                                          \
        for (int j = 0; j < 8; j++) {                                              \
            int u = j * 128 + tid;                                                 \
            int row = u >> 3, seg = u & 7;                                         \
            cp16(bbase + (uint32_t)(row * (AS * 4) + seg * 16), gb + u * 4);       \
        }                                                                          \
        cp_commit();                                                               \
    }

    // warp tiling: 2 wm x 2 wn, warp tile 64 x 64
    const int wm = wid & 1, wn = wid >> 1;
    const int m0 = wm * 64, n0 = wn * 64;
    const int gi = lane >> 2, ti = lane & 3;

    float acc[4][8][4];
#pragma unroll
    for (int mi = 0; mi < 4; mi++)
#pragma unroll
        for (int ni = 0; ni < 8; ni++)
#pragma unroll
            for (int c = 0; c < 4; c++) acc[mi][ni][c] = 0.f;

// one half = 8 B LDS.128 + 2 kf x 4 mi x (4 A LDS.32 + 8 HMMA)
#define MMA_HALF(half)                                                             \
    {                                                                              \
        float4 bq[8];                                                              \
        _Pragma("unroll")                                                          \
        for (int ni = 0; ni < 8; ni++)                                             \
            bq[ni] = *(const float4*)(Bw + ni * 8 * AS + (half) * 4);              \
        _Pragma("unroll")                                                          \
        for (int kf2 = 0; kf2 < 2; kf2++) {                                        \
            const int k0 = ((half) * 2 + kf2) * 8;                                 \
            _Pragma("unroll")                                                      \
            for (int mi = 0; mi < 4; mi++) {                                       \
                const float* ap = Aw + mi * (16 * AS) + k0;                        \
                uint32_t af[4];                                                    \
                af[0] = __float_as_uint(ap[0]);                                    \
                af[1] = __float_as_uint(ap[8 * AS]);                               \
                af[2] = __float_as_uint(ap[4]);                                    \
                af[3] = __float_as_uint(ap[8 * AS + 4]);                           \
                _Pragma("unroll")                                                  \
                for (int ni = 0; ni < 8; ni++) {                                   \
                    uint32_t bf[2];                                                \
                    bf[0] = __float_as_uint(kf2 ? bq[ni].z : bq[ni].x);            \
                    bf[1] = __float_as_uint(kf2 ? bq[ni].w : bq[ni].y);            \
                    mma_tf32(acc[mi][ni], af, bf);                                 \
                }                                                                  \
            }                                                                      \
        }                                                                          \
    }

    LOAD_AB(0, 0);

    for (int i = 0; i < NCHUNK; i++) {
        const int s = i & 1;
        cp_wait0();
        __syncthreads();                 // buf s ready (A+B staged a chunk ago)

        const float* Aw = sA + s * A_BUF + (m0 + gi) * AS + ti;
        const float* Bw = sB + s * B_BUF + (n0 + gi) * AS + 8 * ti;

        MMA_HALF(0)
        if (i + 1 < NCHUNK) LOAD_AB(i + 1, s ^ 1);   // WAR-safe: s^1 reads ended at this iter's barrier
        MMA_HALF(1)
    }

    // ---- epilogue: demodulate + store NHWC ----
#pragma unroll
    for (int mi = 0; mi < 4; mi++) {
        const int ma = m0 + mi * 16 + gi;
        const int mb = ma + 8;
        float* ya  = y + (((size_t)b * HWD + (h0 + (ma >> 6))) * HWD + (ma & 63)) * CH + co0;
        float* yb2 = y + (((size_t)b * HWD + (h0 + (mb >> 6))) * HWD + (mb & 63)) * CH + co0;
#pragma unroll
        for (int ni = 0; ni < 8; ni++) {
            const int col = n0 + ni * 8 + 2 * ti;   // local co
            const float d0 = s_d[col], d1 = s_d[col + 1];
            float2 oa, ob;
            oa.x = acc[mi][ni][0] * d0; oa.y = acc[mi][ni][1] * d1;
            ob.x = acc[mi][ni][2] * d0; ob.y = acc[mi][ni][3] * d1;
            *(float2*)(ya + col)  = oa;
            *(float2*)(yb2 + col) = ob;
        }
    }
#undef LOAD_AB
#undef MMA_HALF
}

// ---------------- launch ----------------
extern "C" void kernel_launch(void* const* d_in, const int* in_sizes, int n_in,
                              void* d_out, int out_size) {
    const float* x     = (const float*)d_in[0];   // [16,64,64,256]
    const float* style = (const float*)d_in[1];   // [16,256]
    const float* kern  = (const float*)d_in[2];   // [3,3,256,256]
    float* y = (float*)d_out;                     // [16,64,64,256]

    static bool attr_set = false;
    if (!attr_set) {
        cudaFuncSetAttribute(conv_kernel, cudaFuncAttributeMaxDynamicSharedMemorySize, SMEM_BYTES);
        attr_set = true;
    }

    k2_kernel<<<CH, CH>>>(kern);
    d_kernel<<<BATCH, CH>>>(style);
    bsprep_kernel<<<(BATCH * KTOT * CH) / 256, 256>>>(kern, style);
    conv_kernel<<<BATCH * 32 * 2, 128, SMEM_BYTES>>>(x, y);
}

// round 17
// speedup vs baseline: 4.1474x; 1.0907x over previous
#include <cuda_runtime.h>
#include <cstdint>

// ---------------- problem dims ----------------
static constexpr int BATCH = 16;
static constexpr int HWD   = 64;
static constexpr int CH    = 256;           // Cin = Cout
static constexpr int KTOT  = 9 * CH;        // 2304
static constexpr int KCH   = 32;            // K per chunk
static constexpr int NCHUNK = KTOT / KCH;   // 72
static constexpr int AS    = 36;            // smem row stride (floats) -> conflict-free

static constexpr int CTA_N = 128;

// ---------------- device scratch ----------------
__device__ float g_K2[CH * CH];
__device__ float g_d[BATCH * CH];
// per-batch modulated B: [b][chunk][co][kperm], tf32-rounded (37.7 MB)
__device__ float g_Bs[(size_t)BATCH * NCHUNK * CH * KCH];

// smem layout (floats): d[128] | A 2x(128*36) | B 2x(128*36)
static constexpr int SM_D = 0;
static constexpr int SM_A = 128;
static constexpr int A_BUF = 128 * AS;      // 4608 floats
static constexpr int SM_B = SM_A + 2 * A_BUF;
static constexpr int B_BUF = 128 * AS;      // 4608 floats
static constexpr int SMEM_FLOATS = SM_B + 2 * B_BUF;   // 18560
static constexpr int SMEM_BYTES  = SMEM_FLOATS * 4;    // 74240 -> 2 CTAs/SM

// ---------------- helpers ----------------
__device__ __forceinline__ float to_tf32(float v) {
    uint32_t u;
    asm("cvt.rna.tf32.f32 %0, %1;" : "=r"(u) : "f"(v));
    return __uint_as_float(u);
}
__device__ __forceinline__ uint32_t smem_u32(const void* p) {
    uint32_t a;
    asm("{ .reg .u64 t; cvta.to.shared.u64 t, %1; cvt.u32.u64 %0, t; }" : "=r"(a) : "l"(p));
    return a;
}
__device__ __forceinline__ void cp16(uint32_t dst_smem, const void* src) {
    asm volatile("cp.async.cg.shared.global [%0], [%1], 16;" :: "r"(dst_smem), "l"(src));
}
// zero-fill variant: copies sz bytes from src, zero-fills the rest of 16
__device__ __forceinline__ void cp16z(uint32_t dst_smem, const void* src, int sz) {
    asm volatile("cp.async.cg.shared.global [%0], [%1], 16, %2;"
                 :: "r"(dst_smem), "l"(src), "r"(sz));
}
__device__ __forceinline__ void cp_commit() {
    asm volatile("cp.async.commit_group;" ::: "memory");
}
__device__ __forceinline__ void cp_wait0() {
    asm volatile("cp.async.wait_group 0;" ::: "memory");
}
__device__ __forceinline__ void mma_tf32(float* c, const uint32_t* a, const uint32_t* b) {
    asm volatile(
        "mma.sync.aligned.m16n8k8.row.col.f32.tf32.tf32.f32 "
        "{%0,%1,%2,%3}, {%4,%5,%6,%7}, {%8,%9}, {%0,%1,%2,%3};"
        : "+f"(c[0]), "+f"(c[1]), "+f"(c[2]), "+f"(c[3])
        : "r"(a[0]), "r"(a[1]), "r"(a[2]), "r"(a[3]), "r"(b[0]), "r"(b[1]));
}

// ---------------- prep kernels ----------------
__global__ void k2_kernel(const float* __restrict__ kern) {
    int co = threadIdx.x, ci = blockIdx.x;
    float acc = 0.f;
#pragma unroll
    for (int tap = 0; tap < 9; tap++) {
        float v = kern[(tap * CH + ci) * CH + co];
        acc += v * v;
    }
    g_K2[ci * CH + co] = acc;
}

__global__ void d_kernel(const float* __restrict__ style) {
    __shared__ float s2[CH];
    int b = blockIdx.x, t = threadIdx.x;
    float s = style[b * CH + t] + 1.0f;
    s2[t] = s * s;
    __syncthreads();
    float acc = 0.f;
#pragma unroll 8
    for (int ci = 0; ci < CH; ci++) acc += s2[ci] * g_K2[ci * CH + t];
    g_d[b * CH + t] = rsqrtf(acc + 1e-8f);
}

// per-batch modulated B pack, COALESCED:
// one thread per (b, chunk, co); permutation done in registers; 128B
// contiguous write per thread; warp reads of kern are coalesced (co fastest).
__global__ void bsprep_kernel(const float* __restrict__ kern, const float* __restrict__ style) {
    int e = blockIdx.x * 256 + threadIdx.x;   // 294912 = 16*72*256
    int co   = e & 255;
    int rest = e >> 8;                        // b*NCHUNK + chunk
    int chunk = rest % NCHUNK;
    int b     = rest / NCHUNK;
    int sub   = chunk & 7;                    // ci0 = sub*32

    const float* sb = style + b * CH + sub * KCH;
    float v[KCH];
#pragma unroll
    for (int kk = 0; kk < KCH; kk++) {
        int k = chunk * KCH + kk;
        float val = kern[(size_t)k * CH + co] * (sb[kk] + 1.0f);   // sb[kk]: warp-broadcast
        int p = 8 * (kk & 3) + (kk >> 2);
        v[p] = to_tf32(val);
    }
    float* out = g_Bs + ((size_t)rest * CH + co) * KCH;
#pragma unroll
    for (int q = 0; q < 8; q++)
        *(float4*)(out + 4 * q) = make_float4(v[4 * q], v[4 * q + 1], v[4 * q + 2], v[4 * q + 3]);
}

// ---------------- main kernel ----------------
// Grid: 1024 CTAs = 16 b x 32 mtiles x 2 ntiles. CTA: M=128 x N=128, K=2304.
// 128 threads = 4 warps (2 M x 2 N), warp tile 64 x 64. 2 CTAs/SM.
// A raw x via zero-fill cp.async (modulation folded into B). Low reg pressure.
__global__ void __launch_bounds__(128, 2) conv_kernel(
    const float* __restrict__ x, float* __restrict__ y) {
    extern __shared__ float sm[];
    float* s_d = sm + SM_D;
    float* sA  = sm + SM_A;
    float* sB  = sm + SM_B;
    const uint32_t sA_u32 = smem_u32(sA);
    const uint32_t sB_u32 = smem_u32(sB);

    const int tid  = threadIdx.x;
    const int lane = tid & 31;
    const int wid  = tid >> 5;
    const int b    = blockIdx.x >> 6;
    const int mt   = (blockIdx.x >> 1) & 31;
    const int nt   = blockIdx.x & 1;
    const int h0   = mt * 2;
    const int co0  = nt * CTA_N;

    if (tid < CTA_N) s_d[tid] = g_d[b * CH + co0 + tid];

    const float* xb  = x + (size_t)b * HWD * HWD * CH;
    const float* gbs = g_Bs + ((size_t)b * NCHUNK) * (CH * KCH) + (size_t)co0 * KCH;

    const int r_base = tid >> 3;          // A row for j: r_base + j*16
    const int v_     = tid & 7;           // 16B segment

// stage A (zero-fill cp.async from raw x) + B (from g_Bs); one commit
#define LOAD_AB(chunk, sbuf)                                                       \
    {                                                                              \
        int tap = (chunk) >> 3, sub = (chunk) & 7;                                 \
        int kh = tap / 3 - 1, kw = tap % 3 - 1;                                    \
        int ci0 = sub * KCH;                                                       \
        uint32_t abase = sA_u32 + (uint32_t)(sbuf) * (A_BUF * 4);                  \
        _Pragma("unroll")                                                          \
        for (int j = 0; j < 8; j++) {                                              \
            int r = r_base + j * 16;                                               \
            int hi = h0 + (r >> 6) + kh, wi = (r & 63) + kw;                       \
            int ok = ((unsigned)hi < (unsigned)HWD) & ((unsigned)wi < (unsigned)HWD); \
            int hc = ok ? hi : 0, wc = ok ? wi : 0;                                \
            cp16z(abase + (uint32_t)((r * AS + v_ * 4) * 4),                       \
                  xb + ((size_t)(hc * HWD + wc)) * CH + ci0 + v_ * 4, ok ? 16 : 0);\
        }                                                                          \
        const float* gb = gbs + (size_t)(chunk) * (CH * KCH);                      \
        uint32_t bbase = sB_u32 + (uint32_t)(sbuf) * (B_BUF * 4);                  \
        _Pragma("unroll")                                                          \
        for (int j = 0; j < 8; j++) {                                              \
            int u = j * 128 + tid;                                                 \
            int row = u >> 3, seg = u & 7;                                         \
            cp16(bbase + (uint32_t)(row * (AS * 4) + seg * 16), gb + u * 4);       \
        }                                                                          \
        cp_commit();                                                               \
    }

    // warp tiling: 2 wm x 2 wn, warp tile 64 x 64
    const int wm = wid & 1, wn = wid >> 1;
    const int m0 = wm * 64, n0 = wn * 64;
    const int gi = lane >> 2, ti = lane & 3;

    float acc[4][8][4];
#pragma unroll
    for (int mi = 0; mi < 4; mi++)
#pragma unroll
        for (int ni = 0; ni < 8; ni++)
#pragma unroll
            for (int c = 0; c < 4; c++) acc[mi][ni][c] = 0.f;

// one half = 8 B LDS.128 + 2 kf x 4 mi x (4 A LDS.32 + 8 HMMA)
#define MMA_HALF(half)                                                             \
    {                                                                              \
        float4 bq[8];                                                              \
        _Pragma("unroll")                                                          \
        for (int ni = 0; ni < 8; ni++)                                             \
            bq[ni] = *(const float4*)(Bw + ni * 8 * AS + (half) * 4);              \
        _Pragma("unroll")                                                          \
        for (int kf2 = 0; kf2 < 2; kf2++) {                                        \
            const int k0 = ((half) * 2 + kf2) * 8;                                 \
            _Pragma("unroll")                                                      \
            for (int mi = 0; mi < 4; mi++) {                                       \
                const float* ap = Aw + mi * (16 * AS) + k0;                        \
                uint32_t af[4];                                                    \
                af[0] = __float_as_uint(ap[0]);                                    \
                af[1] = __float_as_uint(ap[8 * AS]);                               \
                af[2] = __float_as_uint(ap[4]);                                    \
                af[3] = __float_as_uint(ap[8 * AS + 4]);                           \
                _Pragma("unroll")                                                  \
                for (int ni = 0; ni < 8; ni++) {                                   \
                    uint32_t bf[2];                                                \
                    bf[0] = __float_as_uint(kf2 ? bq[ni].z : bq[ni].x);            \
                    bf[1] = __float_as_uint(kf2 ? bq[ni].w : bq[ni].y);            \
                    mma_tf32(acc[mi][ni], af, bf);                                 \
                }                                                                  \
            }                                                                      \
        }                                                                          \
    }

    LOAD_AB(0, 0);

    for (int i = 0; i < NCHUNK; i++) {
        const int s = i & 1;
        cp_wait0();
        __syncthreads();                 // buf s ready (A+B staged a chunk ago)

        const float* Aw = sA + s * A_BUF + (m0 + gi) * AS + ti;
        const float* Bw = sB + s * B_BUF + (n0 + gi) * AS + 8 * ti;

        MMA_HALF(0)
        if (i + 1 < NCHUNK) LOAD_AB(i + 1, s ^ 1);   // WAR-safe: s^1 reads ended at this iter's barrier
        MMA_HALF(1)
    }

    // ---- epilogue: demodulate + store NHWC ----
#pragma unroll
    for (int mi = 0; mi < 4; mi++) {
        const int ma = m0 + mi * 16 + gi;
        const int mb = ma + 8;
        float* ya  = y + (((size_t)b * HWD + (h0 + (ma >> 6))) * HWD + (ma & 63)) * CH + co0;
        float* yb2 = y + (((size_t)b * HWD + (h0 + (mb >> 6))) * HWD + (mb & 63)) * CH + co0;
#pragma unroll
        for (int ni = 0; ni < 8; ni++) {
            const int col = n0 + ni * 8 + 2 * ti;   // local co
            const float d0 = s_d[col], d1 = s_d[col + 1];
            float2 oa, ob;
            oa.x = acc[mi][ni][0] * d0; oa.y = acc[mi][ni][1] * d1;
            ob.x = acc[mi][ni][2] * d0; ob.y = acc[mi][ni][3] * d1;
            *(float2*)(ya + col)  = oa;
            *(float2*)(yb2 + col) = ob;
        }
    }
#undef LOAD_AB
#undef MMA_HALF
}

// ---------------- launch ----------------
extern "C" void kernel_launch(void* const* d_in, const int* in_sizes, int n_in,
                              void* d_out, int out_size) {
    const float* x     = (const float*)d_in[0];   // [16,64,64,256]
    const float* style = (const float*)d_in[1];   // [16,256]
    const float* kern  = (const float*)d_in[2];   // [3,3,256,256]
    float* y = (float*)d_out;                     // [16,64,64,256]

    static bool attr_set = false;
    if (!attr_set) {
        cudaFuncSetAttribute(conv_kernel, cudaFuncAttributeMaxDynamicSharedMemorySize, SMEM_BYTES);
        attr_set = true;
    }

    k2_kernel<<<CH, CH>>>(kern);
    d_kernel<<<BATCH, CH>>>(style);
    bsprep_kernel<<<(BATCH * NCHUNK * CH) / 256, 256>>>(kern, style);
    conv_kernel<<<BATCH * 32 * 2, 128, SMEM_BYTES>>>(x, y);
}